// round 16
// baseline (speedup 1.0000x reference)
#include <cuda_runtime.h>
#include <cuda_bf16.h>
#include <math.h>
#include <cstdint>

#define B 64
#define H 2048
#define D 512
#define HID 512
#define M_TOTAL (B*H)
#define MASK_FILL_F (-4294967295.0f)
#define NCLUSTERS 74
#define NTILES 512            // M-tiles of 256 rows (one cluster each)

// Arch feature gate: tcgen05/TMEM only exist in the sm_103a/sm_100a passes.
#if defined(__CUDA_ARCH_FEAT_SM103_ALL) || defined(__CUDA_ARCH_FEAT_SM100_ALL) || defined(__CUDA_ARCH_FEAT_SM101_ALL)
#define TC_OK 1
#else
#define TC_OK 0
#endif

#define SW128(o) ((o) ^ (((o) >> 3) & 0x70))

#if TC_OK
__device__ __forceinline__ uint32_t smem_to_u32(const void* p) {
    uint32_t a;
    asm("{ .reg .u64 t; cvta.to.shared.u64 t, %1; cvt.u32.u64 %0, t; }"
        : "=r"(a) : "l"(p));
    return a;
}
__device__ __forceinline__ uint32_t elect_one_pred() {
    uint32_t pred;
    asm volatile("{\n\t.reg .pred p;\n\telect.sync _|p, 0xFFFFFFFF;\n\t"
                 "selp.b32 %0, 1, 0, p;\n\t}" : "=r"(pred));
    return pred;
}
__device__ __forceinline__ uint32_t cluster_rank() {
    uint32_t r;
    asm("mov.u32 %0, %%cluster_ctarank;" : "=r"(r));
    return r;
}
#define TCGEN05_ALLOC_CG2(sa, n) \
    asm volatile("tcgen05.alloc.cta_group::2.sync.aligned.shared::cta.b32 [%0], %1;" \
                 :: "r"((uint32_t)(sa)), "r"((uint32_t)(n)) : "memory")
#define TCGEN05_DEALLOC_CG2(ta, n) \
    asm volatile("tcgen05.dealloc.cta_group::2.sync.aligned.b32 %0, %1;" :: "r"(ta), "r"((uint32_t)(n)))
#define TCGEN05_RELINQUISH_CG2() \
    asm volatile("tcgen05.relinquish_alloc_permit.cta_group::2.sync.aligned;")
#define TCGEN05_COMMIT_MC_CG2(mb, mask) \
    asm volatile("tcgen05.commit.cta_group::2.mbarrier::arrive::one.shared::cluster.multicast::cluster.b64 [%0], %1;" \
                 :: "r"((uint32_t)(mb)), "h"((uint16_t)(mask)) : "memory")
#define TCGEN05_WAIT_LD()  asm volatile("tcgen05.wait::ld.sync.aligned;" ::: "memory")
#define TCGEN05_FENCE_BEFORE() asm volatile("tcgen05.fence::before_thread_sync;" ::: "memory")
#define TCGEN05_FENCE_AFTER()  asm volatile("tcgen05.fence::after_thread_sync;" ::: "memory")
#define FENCE_ASYNC_SHARED() asm volatile("fence.proxy.async.shared::cta;" ::: "memory")
#define CLUSTER_SYNC() do { \
    asm volatile("barrier.cluster.arrive.aligned;" ::: "memory"); \
    asm volatile("barrier.cluster.wait.aligned;" ::: "memory"); } while (0)
#define MBARRIER_INIT(mb, cnt) \
    asm volatile("mbarrier.init.shared.b64 [%0], %1;" :: "r"((uint32_t)(mb)), "r"((uint32_t)(cnt)) : "memory")
#define MBARRIER_EXPECT_TX(mb, bytes) \
    asm volatile("mbarrier.arrive.expect_tx.shared.b64 _, [%0], %1;" \
                 :: "r"((uint32_t)(mb)), "r"((uint32_t)(bytes)) : "memory")
#define MBARRIER_ARRIVE_CLUSTER(addr, rank) \
    asm volatile("{\n\t.reg .b32 r;\n\tmapa.shared::cluster.u32 r, %0, %1;\n\t" \
        "mbarrier.arrive.shared::cluster.b64 _, [r];\n\t}" \
        :: "r"((uint32_t)(addr)), "r"((uint32_t)(rank)) : "memory")
#define CP_ASYNC_BULK(dst, src, bytes, mb) \
    asm volatile("cp.async.bulk.shared::cta.global.mbarrier::complete_tx::bytes " \
                 "[%0], [%1], %2, [%3];" \
                 :: "r"((uint32_t)(dst)), "l"(src), "r"((uint32_t)(bytes)), \
                    "r"((uint32_t)(mb)) : "memory")
#define MBARRIER_WAIT_PARITY(mb, ph) do { \
    uint32_t _mb = (uint32_t)(mb); uint32_t _ph = (uint32_t)(ph); uint32_t _done; \
    asm volatile("{\n\t.reg .pred p;\n\t" \
        "mbarrier.try_wait.parity.acquire.cta.shared::cta.b64 p, [%1], %2;\n\t" \
        "selp.b32 %0, 1, 0, p;\n\t}" : "=r"(_done) : "r"(_mb), "r"(_ph) : "memory"); \
    if (!_done) { \
        asm volatile("{\n\t.reg .pred P1;\n\t" \
            "WL_%=:\n\t" \
            "mbarrier.try_wait.parity.acquire.cta.shared::cta.b64 P1, [%0], %1, 0x989680;\n\t" \
            "@P1 bra.uni WD_%=;\n\t" \
            "bra.uni WL_%=;\n\t" \
            "WD_%=:\n\t}" :: "r"(_mb), "r"(_ph) : "memory"); \
    } } while (0)
#define MBARRIER_WAIT_PARITY_CLU(mb, ph) do { \
    uint32_t _mb = (uint32_t)(mb); uint32_t _ph = (uint32_t)(ph); uint32_t _done; \
    asm volatile("{\n\t.reg .pred p;\n\t" \
        "mbarrier.try_wait.parity.acquire.cluster.shared::cta.b64 p, [%1], %2;\n\t" \
        "selp.b32 %0, 1, 0, p;\n\t}" : "=r"(_done) : "r"(_mb), "r"(_ph) : "memory"); \
    if (!_done) { \
        asm volatile("{\n\t.reg .pred P1;\n\t" \
            "WL_%=:\n\t" \
            "mbarrier.try_wait.parity.acquire.cluster.shared::cta.b64 P1, [%0], %1, 0x989680;\n\t" \
            "@P1 bra.uni WD_%=;\n\t" \
            "bra.uni WL_%=;\n\t" \
            "WD_%=:\n\t}" :: "r"(_mb), "r"(_ph) : "memory"); \
    } } while (0)
#define TCGEN05_LD_32X32B_X32(r, ta) \
    asm volatile("tcgen05.ld.sync.aligned.32x32b.x32.b32 " \
        "{%0, %1, %2, %3, %4, %5, %6, %7, %8, %9, %10, %11, %12, %13, %14, %15, " \
        " %16, %17, %18, %19, %20, %21, %22, %23, %24, %25, %26, %27, %28, %29, %30, %31}, [%32];" \
        : "=r"((r)[0]),  "=r"((r)[1]),  "=r"((r)[2]),  "=r"((r)[3]), \
          "=r"((r)[4]),  "=r"((r)[5]),  "=r"((r)[6]),  "=r"((r)[7]), \
          "=r"((r)[8]),  "=r"((r)[9]),  "=r"((r)[10]), "=r"((r)[11]), \
          "=r"((r)[12]), "=r"((r)[13]), "=r"((r)[14]), "=r"((r)[15]), \
          "=r"((r)[16]), "=r"((r)[17]), "=r"((r)[18]), "=r"((r)[19]), \
          "=r"((r)[20]), "=r"((r)[21]), "=r"((r)[22]), "=r"((r)[23]), \
          "=r"((r)[24]), "=r"((r)[25]), "=r"((r)[26]), "=r"((r)[27]), \
          "=r"((r)[28]), "=r"((r)[29]), "=r"((r)[30]), "=r"((r)[31]) \
        : "r"(ta))

static constexpr uint64_t SMEM_DESC_BASE_SW128 =
    (uint64_t(2)  << 61) | (uint64_t(1) << 46) | (uint64_t(64) << 32) | (uint64_t(1) << 16);
#define MAKE_SMEM_DESC(a) (SMEM_DESC_BASE_SW128 | ((uint64_t)((a) >> 4) & 0x3FFF))

// idesc kind::f16 cg2: dtype=F32, a/b=BF16, N=256, M=256
static constexpr uint32_t IDESC_BF16_CG2 =
    (1u << 4) | (1u << 7) | (1u << 10) | ((256u / 8) << 17) | ((256u / 16) << 24);

__device__ __forceinline__ void mma_bf16_ss_cg2(uint32_t d, uint64_t ad, uint64_t bd,
                                                uint32_t idesc, unsigned en) {
    asm volatile("{\n\t.reg .pred p;\n\tsetp.ne.u32 p, %5, 0;\n\t"
        "tcgen05.mma.cta_group::2.kind::f16 [%0], %1, %2, %3, "
        "{%4, %4, %4, %4, %4, %4, %4, %4}, p;\n\t}"
        :: "r"(d), "l"(ad), "l"(bd), "r"(idesc), "r"(0u), "r"(en) : "memory");
}
#endif // TC_OK

// ---------------------------------------------------------------------------
// Scratch
// ---------------------------------------------------------------------------
__device__ float    g_gate[B*D];
__device__ float    g_score[B*H];
__device__ __align__(16) unsigned char g_w1s[8*65536];   // bf16 w1^T SW128 images
__device__ int      g_flag_gt1 = 0;
__device__ int      g_flag_other = 0;

// ---------------------------------------------------------------------------
// Kernel S: merged setup — cvt_w1 / gate+zero-out / mask-dtype detect
// ---------------------------------------------------------------------------
__global__ void k_setup(const float* __restrict__ Kmat,
                        const float* __restrict__ W,
                        const float* __restrict__ w1,
                        const unsigned char* __restrict__ mask,
                        float* __restrict__ out) {
    const int blk = blockIdx.x;
    const int tid = threadIdx.x;
    if (blk < 128) {
        int lin = blk * 256 + tid;
        int n     = lin & 511;
        int kq    = (lin >> 9) & 7;
        int chunk = lin >> 12;
        int k0 = chunk*64 + kq*8;
        __nv_bfloat162 t[4];
        #pragma unroll
        for (int j = 0; j < 4; j++) {
            float f0 = w1[(k0 + 2*j    ) * HID + n];
            float f1 = w1[(k0 + 2*j + 1) * HID + n];
            t[j] = __floats2bfloat162_rn(f0, f1);
        }
        uint32_t off = (uint32_t)(n*128 + kq*16);
        *reinterpret_cast<uint4*>(g_w1s + chunk*65536 + SW128(off)) =
            *reinterpret_cast<uint4*>(t);
    } else if (blk < 256) {
        int i = (blk - 128) * 256 + tid;
        int k = i & 511;
        g_gate[i] = W[k*D + k] * Kmat[i];
        out[i] = 0.0f;
    } else {
        int lgt1 = 0, lother = 0;
        int base = (blk - 256) * 2048;
        for (int j = tid; j < 2048; j += 256) {
            int i = base + j;
            unsigned char v = mask[i];
            if (v > 1) lgt1 = 1;
            if (v != 0 && (i & 3) != 0) lother = 1;
        }
        if (__syncthreads_or(lgt1))   { if (tid == 0) atomicOr(&g_flag_gt1, 1); }
        if (__syncthreads_or(lother)) { if (tid == 0) atomicOr(&g_flag_other, 1); }
    }
}

// ---------------------------------------------------------------------------
// Kernel 1: persistent cg2 GEMM + fused relu/w2 epilogue -> g_score.
//   Exact R9 structure (proven 135.9us total); single change: V loads for
//   chunk i+1 are issued at the TOP of each iteration (double-buffered
//   registers) so DRAM latency overlaps the MDONE wait + convert.
// ---------------------------------------------------------------------------
// SMEM map:
#define OFF_TMEM    0
#define MB_MDONE(b) (8  + (b)*8)            // 8, 16
#define MB_BRDY(b)  (24 + (b)*8)            // 24, 32, 40
#define MB_TRDY(b)  (48 + (b)*8)            // 48, 56 (leader, count=2)
#define MB_EPID     64                       // leader, count=2
#define OFF_GATE    128                      // 512 f32
#define OFF_BIAS    2176                     // 512 f32
#define OFF_W2V     4224                     // 512 f32
#define OFF_A(b)    (8192  + (b)*16384)      // 2 x 16 KB bf16 A (SW128)
#define OFF_B(b)    (40960 + (b)*32768)      // 3 x 32 KB bf16 B-half (SW128)
#define SMEM_BYTES  139264

__global__ __launch_bounds__(256, 1) __cluster_dims__(2, 1, 1)
void k_gemm_tc(
        const float* __restrict__ V,
        const float* __restrict__ w1,
        const float* __restrict__ b1,
        const float* __restrict__ w2) {
    extern __shared__ char smem[];
    const int tid = threadIdx.x;

#if TC_OK
    // =================== persistent cg2 tcgen05 bf16 path ===================
    const uint32_t sb = smem_to_u32(smem);
    const int wid = tid >> 5;
    const int lid = tid & 31;
    const uint32_t rank = cluster_rank();
    const int cid = blockIdx.x >> 1;

    float* gs   = (float*)(smem + OFF_GATE);
    float* bias = (float*)(smem + OFF_BIAS);
    float* w2s  = (float*)(smem + OFF_W2V);
    for (int i = tid; i < D; i += 256) { bias[i] = b1[i]; w2s[i] = w2[i]; }

    if (wid == 0) TCGEN05_ALLOC_CG2(sb + OFF_TMEM, 512);
    if (tid == 0) {
        MBARRIER_INIT(sb + MB_MDONE(0), 1); MBARRIER_INIT(sb + MB_MDONE(1), 1);
        MBARRIER_INIT(sb + MB_BRDY(0), 1);  MBARRIER_INIT(sb + MB_BRDY(1), 1);
        MBARRIER_INIT(sb + MB_BRDY(2), 1);
        MBARRIER_INIT(sb + MB_TRDY(0), 2);  MBARRIER_INIT(sb + MB_TRDY(1), 2);
        MBARRIER_INIT(sb + MB_EPID, 2);
    }
    __syncthreads();
    CLUSTER_SYNC();

    uint32_t tmem;
    asm volatile("ld.shared.b32 %0, [%1];" : "=r"(tmem) : "r"(sb + OFF_TMEM));

    // B-half sources for this rank (rows [128r,128r+128) and [256+128r,384+128r))
    const unsigned char* bsrc0 = g_w1s + rank*16384;
    const unsigned char* bsrc1 = g_w1s + 32768 + rank*16384;

    const int kq  = tid & 7;
    const int mb_ = tid >> 3;

    int mdpar[2] = {0, 0};
    int bpar[3]  = {0, 0, 0};
    int tpar[2]  = {0, 0};
    int epar     = 0;
    int b3 = 0;              // global chunk counter mod 3
    bool first = true;
    float4 vbuf[2][8];       // double-buffered V registers (chunk parity i&1)

    for (int t = cid; t < NTILES; t += NCLUSTERS) {
        const int row0 = t*256 + rank*128;
        const int b = row0 >> 11;
        const bool hasNext = (t + NCLUSTERS) < NTILES;
        const float* Vbase = V + (long long)row0 * D;

        // gate for this tile's batch
        for (int i = tid; i < D; i += 256) gs[i] = g_gate[b*D + i];
        __syncthreads();

        if (first) {
            // Prologue: B kchunks 0,1,2 into bufs 0,1,2; V chunk 0 into regs
            if (tid == 0) {
                #pragma unroll
                for (int c = 0; c < 3; c++) {
                    MBARRIER_EXPECT_TX(sb + MB_BRDY(c), 32768u);
                    CP_ASYNC_BULK(sb + OFF_B(c),         (const void*)(bsrc0 + c*65536),
                                  16384u, sb + MB_BRDY(c));
                    CP_ASYNC_BULK(sb + OFF_B(c) + 16384, (const void*)(bsrc1 + c*65536),
                                  16384u, sb + MB_BRDY(c));
                }
            }
            #pragma unroll
            for (int l = 0; l < 4; l++) {
                const float* p = Vbase + (long long)(mb_ + l*32)*D + kq*8;
                vbuf[0][2*l]   = *reinterpret_cast<const float4*>(p);
                vbuf[0][2*l+1] = *reinterpret_cast<const float4*>(p + 4);
            }
            first = false;
        } else {
            // B for kchunks 1,2 of this tile (bufs b3+1, b3+2 freed by epilogue)
            if (tid == 0) {
                #pragma unroll
                for (int c = 1; c <= 2; c++) {
                    int nb = b3 + c; nb -= (nb >= 3) ? 3 : 0;
                    MBARRIER_EXPECT_TX(sb + MB_BRDY(nb), 32768u);
                    CP_ASYNC_BULK(sb + OFF_B(nb),         (const void*)(bsrc0 + c*65536),
                                  16384u, sb + MB_BRDY(nb));
                    CP_ASYNC_BULK(sb + OFF_B(nb) + 16384, (const void*)(bsrc1 + c*65536),
                                  16384u, sb + MB_BRDY(nb));
                }
            }
            // vbuf[0] already holds this tile's chunk 0 (loaded at prev tile i==7)
        }

        for (int i = 0; i < 8; i++) {
            const int abuf = i & 1;

            // Issue NEXT chunk's V loads FIRST — independent of MDONE, so the
            // ~600-cycle DRAM latency overlaps the wait + convert below.
            if (i < 7) {
                #pragma unroll
                for (int l = 0; l < 4; l++) {
                    const float* p = Vbase + (long long)(mb_ + l*32)*D + (i+1)*64 + kq*8;
                    vbuf[(i+1)&1][2*l]   = *reinterpret_cast<const float4*>(p);
                    vbuf[(i+1)&1][2*l+1] = *reinterpret_cast<const float4*>(p + 4);
                }
            } else if (hasNext) {
                const float* nVbase = V + (long long)((t + NCLUSTERS)*256 + rank*128) * D;
                #pragma unroll
                for (int l = 0; l < 4; l++) {
                    const float* p = nVbase + (long long)(mb_ + l*32)*D + kq*8;
                    vbuf[0][2*l]   = *reinterpret_cast<const float4*>(p);
                    vbuf[0][2*l+1] = *reinterpret_cast<const float4*>(p + 4);
                }
            }

            if (i >= 2) {
                MBARRIER_WAIT_PARITY(sb + MB_MDONE(abuf), mdpar[abuf]);
                mdpar[abuf] ^= 1;
                // prefetch B for next global chunk (kchunk i+1, or 0 of next tile)
                if (tid == 0 && (i < 7 || hasNext)) {
                    int nk = (i + 1) & 7;
                    int nb = b3 + 1; nb -= (nb >= 3) ? 3 : 0;
                    MBARRIER_EXPECT_TX(sb + MB_BRDY(nb), 32768u);
                    CP_ASYNC_BULK(sb + OFF_B(nb),         (const void*)(bsrc0 + nk*65536),
                                  16384u, sb + MB_BRDY(nb));
                    CP_ASYNC_BULK(sb + OFF_B(nb) + 16384, (const void*)(bsrc1 + nk*65536),
                                  16384u, sb + MB_BRDY(nb));
                }
            }

            // Convert vbuf[i&1] (chunk i) -> A[abuf], gated, SW128
            {
                const float* gp = gs + i*64 + kq*8;
                float4 gA = *reinterpret_cast<const float4*>(gp);
                float4 gB = *reinterpret_cast<const float4*>(gp + 4);
                #pragma unroll
                for (int l = 0; l < 4; l++) {
                    int m = mb_ + l*32;
                    float4 v0 = vbuf[i&1][2*l], v1 = vbuf[i&1][2*l+1];
                    __nv_bfloat162 tt[4];
                    tt[0] = __floats2bfloat162_rn(v0.x*gA.x, v0.y*gA.y);
                    tt[1] = __floats2bfloat162_rn(v0.z*gA.z, v0.w*gA.w);
                    tt[2] = __floats2bfloat162_rn(v1.x*gB.x, v1.y*gB.y);
                    tt[3] = __floats2bfloat162_rn(v1.z*gB.z, v1.w*gB.w);
                    uint32_t off = (uint32_t)(m*128 + kq*16);
                    *reinterpret_cast<uint4*>(smem + OFF_A(abuf) + SW128(off)) =
                        *reinterpret_cast<uint4*>(tt);
                }
            }

            FENCE_ASYNC_SHARED();
            __syncthreads();

            // Signal thread: local B ready + A stored -> arrive leader TRDY
            if (tid == 32) {
                MBARRIER_WAIT_PARITY(sb + MB_BRDY(b3), bpar[b3]);
                bpar[b3] ^= 1;
                MBARRIER_ARRIVE_CLUSTER(sb + MB_TRDY(abuf), 0);
            }

            // Leader: wait readiness (and prior tile's epilogue for i==0), MMA
            if (rank == 0 && wid == 0) {
                if (i == 0 && t != cid) {
                    MBARRIER_WAIT_PARITY_CLU(sb + MB_EPID, epar);
                    epar ^= 1;
                }
                MBARRIER_WAIT_PARITY_CLU(sb + MB_TRDY(abuf), tpar[abuf]);
                tpar[abuf] ^= 1;
                if (elect_one_pred()) {
                    uint64_t ad = MAKE_SMEM_DESC(sb + OFF_A(abuf));
                    uint64_t bd = MAKE_SMEM_DESC(sb + OFF_B(b3));
                    #pragma unroll
                    for (int ks = 0; ks < 4; ks++) {
                        unsigned en = (i > 0 || ks > 0) ? 1u : 0u;
                        mma_bf16_ss_cg2(tmem,       ad + ks*2, bd + ks*2,
                                        IDESC_BF16_CG2, en);
                        mma_bf16_ss_cg2(tmem + 256, ad + ks*2, bd + 1024 + ks*2,
                                        IDESC_BF16_CG2, en);
                    }
                    TCGEN05_COMMIT_MC_CG2(sb + MB_MDONE(abuf), 0x3);
                }
            }
            b3++; b3 -= (b3 >= 3) ? 3 : 0;
        }

        // Drain last two chunks' MMAs, then epilogue
        MBARRIER_WAIT_PARITY(sb + MB_MDONE(0), mdpar[0]); mdpar[0] ^= 1;
        MBARRIER_WAIT_PARITY(sb + MB_MDONE(1), mdpar[1]); mdpar[1] ^= 1;
        TCGEN05_FENCE_AFTER();

        if (wid < 4) {
            float s = 0.0f;
            #pragma unroll 1
            for (int c = 0; c < HID; c += 64) {
                uint32_t r0[32], r1[32];
                TCGEN05_LD_32X32B_X32(r0, tmem + c);
                TCGEN05_LD_32X32B_X32(r1, tmem + c + 32);
                TCGEN05_WAIT_LD();
                #pragma unroll
                for (int j = 0; j < 32; j++) {
                    float v0 = __uint_as_float(r0[j]) + bias[c + j];
                    float v1 = __uint_as_float(r1[j]) + bias[c + 32 + j];
                    s += fmaxf(v0, 0.0f) * w2s[c + j];
                    s += fmaxf(v1, 0.0f) * w2s[c + 32 + j];
                }
            }
            TCGEN05_FENCE_BEFORE();
            g_score[row0 + wid*32 + lid] = s;
        }
        __syncthreads();
        // Tell leader both CTAs' epilogues are done (D may be overwritten)
        if (hasNext && tid == 32)
            MBARRIER_ARRIVE_CLUSTER(sb + MB_EPID, 0);
    }

    CLUSTER_SYNC();
    if (wid == 0) {
        TCGEN05_RELINQUISH_CG2();
        TCGEN05_DEALLOC_CG2(tmem, 512);
    }
#else
    // ======================= f32x2 SGEMM fallback (persistent) =============
    float* Xs  = (float*)smem;
    float* Ws  = (float*)(smem + 128*20*4);
    float* gsh = (float*)(smem + 128*20*4 + 16*128*4);
    float* red = gsh + 512;
    const int tx = tid & 15;
    const int ty = tid >> 4;

    for (int mt = blockIdx.x; mt < M_TOTAL/128; mt += gridDim.x) {
        const int row0 = mt * 128;
        const int b = row0 >> 11;
        for (int i = tid; i < D; i += 256) gsh[i] = g_gate[b*D + i];
        __syncthreads();

        float scoreAcc[8];
        #pragma unroll
        for (int i = 0; i < 8; i++) scoreAcc[i] = 0.0f;

        const float* Vblk = V + (long long)row0 * D;

        for (int n0 = 0; n0 < HID; n0 += 128) {
            unsigned long long acc[8][4];
            #pragma unroll
            for (int i = 0; i < 8; i++)
                #pragma unroll
                for (int q = 0; q < 4; q++) acc[i][q] = 0ULL;

            for (int kk = 0; kk < D; kk += 16) {
                #pragma unroll
                for (int l = 0; l < 2; l++) {
                    int lin = tid + l*256;
                    int m   = lin >> 2;
                    int k4  = (lin & 3) << 2;
                    float4 v = *reinterpret_cast<const float4*>(
                                   &Vblk[(long long)m*D + kk + k4]);
                    Xs[m*20 + k4+0] = v.x; Xs[m*20 + k4+1] = v.y;
                    Xs[m*20 + k4+2] = v.z; Xs[m*20 + k4+3] = v.w;
                }
                #pragma unroll
                for (int l = 0; l < 2; l++) {
                    int lin = tid + l*256;
                    int k   = lin >> 5;
                    int n4  = (lin & 31) << 2;
                    float gk = gsh[kk + k];
                    float4 w = *reinterpret_cast<const float4*>(
                                   &w1[(long long)(kk+k)*HID + n0 + n4]);
                    Ws[k*128 + n4+0] = w.x*gk; Ws[k*128 + n4+1] = w.y*gk;
                    Ws[k*128 + n4+2] = w.z*gk; Ws[k*128 + n4+3] = w.w*gk;
                }
                __syncthreads();

                #pragma unroll
                for (int k = 0; k < 16; k++) {
                    unsigned long long bvec[4];
                    const unsigned long long* wr =
                        reinterpret_cast<const unsigned long long*>(&Ws[k*128 + tx*8]);
                    #pragma unroll
                    for (int q = 0; q < 4; q++) bvec[q] = wr[q];
                    #pragma unroll
                    for (int i = 0; i < 8; i++) {
                        float a = Xs[(ty*8 + i)*20 + k];
                        unsigned long long a2;
                        asm("mov.b64 %0, {%1, %1};" : "=l"(a2) : "f"(a));
                        #pragma unroll
                        for (int q = 0; q < 4; q++)
                            asm("fma.rn.f32x2 %0, %1, %2, %0;"
                                : "+l"(acc[i][q]) : "l"(a2), "l"(bvec[q]));
                    }
                }
                __syncthreads();
            }

            float b1v[8], w2v[8];
            #pragma unroll
            for (int j = 0; j < 8; j++) {
                b1v[j] = b1[n0 + tx*8 + j];
                w2v[j] = w2[n0 + tx*8 + j];
            }
            #pragma unroll
            for (int i = 0; i < 8; i++) {
                float s = 0.0f;
                #pragma unroll
                for (int q = 0; q < 4; q++) {
                    float2 v = *reinterpret_cast<float2*>(&acc[i][q]);
                    float c0 = v.x + b1v[q*2+0];
                    float c1 = v.y + b1v[q*2+1];
                    s += fmaxf(c0, 0.0f) * w2v[q*2+0] + fmaxf(c1, 0.0f) * w2v[q*2+1];
                }
                scoreAcc[i] += s;
            }
        }

        #pragma unroll
        for (int i = 0; i < 8; i++) red[(ty*8 + i)*17 + tx] = scoreAcc[i];
        __syncthreads();
        if (tid < 128) {
            float s = 0.0f;
            #pragma unroll
            for (int tq = 0; tq < 16; tq++) s += red[tid*17 + tq];
            g_score[row0 + tid] = s;
        }
        __syncthreads();
    }
#endif
}

// ---------------------------------------------------------------------------
// Kernel 2: masked softmax over h per batch, alpha stored in place
// ---------------------------------------------------------------------------
__global__ __launch_bounds__(256) void k_softmax(const void* __restrict__ mask_raw) {
    const int b   = blockIdx.x;
    const int tid = threadIdx.x;
    __shared__ float sh[256];

    const int mode = g_flag_gt1 ? 2 : (g_flag_other ? 0 : 1);
    const unsigned char* m8  = (const unsigned char*)mask_raw;
    const int*           m32 = (const int*)mask_raw;
    const float*         mf  = (const float*)mask_raw;

    float s[8];
    float mx = -3.0e38f;
    #pragma unroll
    for (int l = 0; l < 8; l++) {
        int idx = b*H + tid + l*256;
        bool masked;
        if (mode == 1)      masked = (m32[idx] != 0);
        else if (mode == 2) masked = (mf[idx] != 0.0f);
        else                masked = (m8[idx] != 0);
        float v = g_score[idx];
        if (masked) v = MASK_FILL_F;
        s[l] = v;
        mx = fmaxf(mx, v);
    }
    sh[tid] = mx; __syncthreads();
    for (int off = 128; off > 0; off >>= 1) {
        if (tid < off) sh[tid] = fmaxf(sh[tid], sh[tid + off]);
        __syncthreads();
    }
    mx = sh[0];
    __syncthreads();

    float e[8], sum = 0.0f;
    #pragma unroll
    for (int l = 0; l < 8; l++) { e[l] = expf(s[l] - mx); sum += e[l]; }
    sh[tid] = sum; __syncthreads();
    for (int off = 128; off > 0; off >>= 1) {
        if (tid < off) sh[tid] += sh[tid + off];
        __syncthreads();
    }
    float inv = 1.0f / sh[0];
    #pragma unroll
    for (int l = 0; l < 8; l++) g_score[b*H + tid + l*256] = e[l] * inv;
}

// ---------------------------------------------------------------------------
// Kernel 3: attn[b,d] = sum_h alpha[b,h] * V[b,h,d]   (R9-proven)
// ---------------------------------------------------------------------------
__global__ __launch_bounds__(128) void k_wsum(const float* __restrict__ V,
                                              float* __restrict__ out) {
    const int b   = blockIdx.x;
    const int h0  = blockIdx.y * 64;
    const int tid = threadIdx.x;
    __shared__ float al[64];
    if (tid < 64) al[tid] = g_score[b*H + h0 + tid];
    __syncthreads();

    const float4* Vb = reinterpret_cast<const float4*>(
        V + ((long long)b*H + h0) * D);
    float4 acc = make_float4(0.f, 0.f, 0.f, 0.f);
    #pragma unroll 8
    for (int h = 0; h < 64; h++) {
        float a = al[h];
        float4 v = Vb[(long long)h*128 + tid];
        acc.x = fmaf(a, v.x, acc.x);
        acc.y = fmaf(a, v.y, acc.y);
        acc.z = fmaf(a, v.z, acc.z);
        acc.w = fmaf(a, v.w, acc.w);
    }
    float* o = out + b*D + tid*4;
    atomicAdd(o + 0, acc.x);
    atomicAdd(o + 1, acc.y);
    atomicAdd(o + 2, acc.z);
    atomicAdd(o + 3, acc.w);
}

// ---------------------------------------------------------------------------
extern "C" void kernel_launch(void* const* d_in, const int* in_sizes, int n_in,
                              void* d_out, int out_size) {
    const float* Kmat = (const float*)d_in[0];
    const float* V    = (const float*)d_in[1];
    const void*  mask = d_in[2];
    const float* W    = (const float*)d_in[3];
    const float* w1   = (const float*)d_in[4];
    const float* b1   = (const float*)d_in[5];
    const float* w2   = (const float*)d_in[6];
    // b2 is a uniform score shift -> softmax-invariant, unused.
    float* out = (float*)d_out;

    cudaFuncSetAttribute(k_gemm_tc, cudaFuncAttributeMaxDynamicSharedMemorySize,
                         SMEM_BYTES);

    k_setup<<<320, 256>>>(Kmat, W, w1, (const unsigned char*)mask, out);
    k_gemm_tc<<<NCLUSTERS*2, 256, SMEM_BYTES>>>(V, w1, b1, w2);
    k_softmax<<<B, 256>>>(mask);
    k_wsum<<<dim3(B, 32), 128>>>(V, out);
}

// round 17
// speedup vs baseline: 1.4200x; 1.4200x over previous
#include <cuda_runtime.h>
#include <cuda_bf16.h>
#include <math.h>
#include <cstdint>

#define B 64
#define H 2048
#define D 512
#define HID 512
#define M_TOTAL (B*H)
#define MASK_FILL_F (-4294967295.0f)
#define NCLUSTERS 74
#define NTILES 512            // M-tiles of 256 rows (one cluster each)

// Arch feature gate: tcgen05/TMEM only exist in the sm_103a/sm_100a passes.
#if defined(__CUDA_ARCH_FEAT_SM103_ALL) || defined(__CUDA_ARCH_FEAT_SM100_ALL) || defined(__CUDA_ARCH_FEAT_SM101_ALL)
#define TC_OK 1
#else
#define TC_OK 0
#endif

#define SW128(o) ((o) ^ (((o) >> 3) & 0x70))

#if TC_OK
__device__ __forceinline__ uint32_t smem_to_u32(const void* p) {
    uint32_t a;
    asm("{ .reg .u64 t; cvta.to.shared.u64 t, %1; cvt.u32.u64 %0, t; }"
        : "=r"(a) : "l"(p));
    return a;
}
__device__ __forceinline__ uint32_t elect_one_pred() {
    uint32_t pred;
    asm volatile("{\n\t.reg .pred p;\n\telect.sync _|p, 0xFFFFFFFF;\n\t"
                 "selp.b32 %0, 1, 0, p;\n\t}" : "=r"(pred));
    return pred;
}
__device__ __forceinline__ uint32_t cluster_rank() {
    uint32_t r;
    asm("mov.u32 %0, %%cluster_ctarank;" : "=r"(r));
    return r;
}
#define TCGEN05_ALLOC_CG2(sa, n) \
    asm volatile("tcgen05.alloc.cta_group::2.sync.aligned.shared::cta.b32 [%0], %1;" \
                 :: "r"((uint32_t)(sa)), "r"((uint32_t)(n)) : "memory")
#define TCGEN05_DEALLOC_CG2(ta, n) \
    asm volatile("tcgen05.dealloc.cta_group::2.sync.aligned.b32 %0, %1;" :: "r"(ta), "r"((uint32_t)(n)))
#define TCGEN05_RELINQUISH_CG2() \
    asm volatile("tcgen05.relinquish_alloc_permit.cta_group::2.sync.aligned;")
#define TCGEN05_COMMIT_MC_CG2(mb, mask) \
    asm volatile("tcgen05.commit.cta_group::2.mbarrier::arrive::one.shared::cluster.multicast::cluster.b64 [%0], %1;" \
                 :: "r"((uint32_t)(mb)), "h"((uint16_t)(mask)) : "memory")
#define TCGEN05_WAIT_LD()  asm volatile("tcgen05.wait::ld.sync.aligned;" ::: "memory")
#define TCGEN05_FENCE_BEFORE() asm volatile("tcgen05.fence::before_thread_sync;" ::: "memory")
#define TCGEN05_FENCE_AFTER()  asm volatile("tcgen05.fence::after_thread_sync;" ::: "memory")
#define FENCE_ASYNC_SHARED() asm volatile("fence.proxy.async.shared::cta;" ::: "memory")
#define CLUSTER_SYNC() do { \
    asm volatile("barrier.cluster.arrive.aligned;" ::: "memory"); \
    asm volatile("barrier.cluster.wait.aligned;" ::: "memory"); } while (0)
#define MBARRIER_INIT(mb, cnt) \
    asm volatile("mbarrier.init.shared.b64 [%0], %1;" :: "r"((uint32_t)(mb)), "r"((uint32_t)(cnt)) : "memory")
#define MBARRIER_EXPECT_TX(mb, bytes) \
    asm volatile("mbarrier.arrive.expect_tx.shared.b64 _, [%0], %1;" \
                 :: "r"((uint32_t)(mb)), "r"((uint32_t)(bytes)) : "memory")
#define MBARRIER_ARRIVE_CLUSTER(addr, rank) \
    asm volatile("{\n\t.reg .b32 r;\n\tmapa.shared::cluster.u32 r, %0, %1;\n\t" \
        "mbarrier.arrive.shared::cluster.b64 _, [r];\n\t}" \
        :: "r"((uint32_t)(addr)), "r"((uint32_t)(rank)) : "memory")
#define CP_ASYNC_BULK(dst, src, bytes, mb) \
    asm volatile("cp.async.bulk.shared::cta.global.mbarrier::complete_tx::bytes " \
                 "[%0], [%1], %2, [%3];" \
                 :: "r"((uint32_t)(dst)), "l"(src), "r"((uint32_t)(bytes)), \
                    "r"((uint32_t)(mb)) : "memory")
#define MBARRIER_WAIT_PARITY(mb, ph) do { \
    uint32_t _mb = (uint32_t)(mb); uint32_t _ph = (uint32_t)(ph); uint32_t _done; \
    asm volatile("{\n\t.reg .pred p;\n\t" \
        "mbarrier.try_wait.parity.acquire.cta.shared::cta.b64 p, [%1], %2;\n\t" \
        "selp.b32 %0, 1, 0, p;\n\t}" : "=r"(_done) : "r"(_mb), "r"(_ph) : "memory"); \
    if (!_done) { \
        asm volatile("{\n\t.reg .pred P1;\n\t" \
            "WL_%=:\n\t" \
            "mbarrier.try_wait.parity.acquire.cta.shared::cta.b64 P1, [%0], %1, 0x989680;\n\t" \
            "@P1 bra.uni WD_%=;\n\t" \
            "bra.uni WL_%=;\n\t" \
            "WD_%=:\n\t}" :: "r"(_mb), "r"(_ph) : "memory"); \
    } } while (0)
#define MBARRIER_WAIT_PARITY_CLU(mb, ph) do { \
    uint32_t _mb = (uint32_t)(mb); uint32_t _ph = (uint32_t)(ph); uint32_t _done; \
    asm volatile("{\n\t.reg .pred p;\n\t" \
        "mbarrier.try_wait.parity.acquire.cluster.shared::cta.b64 p, [%1], %2;\n\t" \
        "selp.b32 %0, 1, 0, p;\n\t}" : "=r"(_done) : "r"(_mb), "r"(_ph) : "memory"); \
    if (!_done) { \
        asm volatile("{\n\t.reg .pred P1;\n\t" \
            "WL_%=:\n\t" \
            "mbarrier.try_wait.parity.acquire.cluster.shared::cta.b64 P1, [%0], %1, 0x989680;\n\t" \
            "@P1 bra.uni WD_%=;\n\t" \
            "bra.uni WL_%=;\n\t" \
            "WD_%=:\n\t}" :: "r"(_mb), "r"(_ph) : "memory"); \
    } } while (0)
#define TCGEN05_LD_32X32B_X32(r, ta) \
    asm volatile("tcgen05.ld.sync.aligned.32x32b.x32.b32 " \
        "{%0, %1, %2, %3, %4, %5, %6, %7, %8, %9, %10, %11, %12, %13, %14, %15, " \
        " %16, %17, %18, %19, %20, %21, %22, %23, %24, %25, %26, %27, %28, %29, %30, %31}, [%32];" \
        : "=r"((r)[0]),  "=r"((r)[1]),  "=r"((r)[2]),  "=r"((r)[3]), \
          "=r"((r)[4]),  "=r"((r)[5]),  "=r"((r)[6]),  "=r"((r)[7]), \
          "=r"((r)[8]),  "=r"((r)[9]),  "=r"((r)[10]), "=r"((r)[11]), \
          "=r"((r)[12]), "=r"((r)[13]), "=r"((r)[14]), "=r"((r)[15]), \
          "=r"((r)[16]), "=r"((r)[17]), "=r"((r)[18]), "=r"((r)[19]), \
          "=r"((r)[20]), "=r"((r)[21]), "=r"((r)[22]), "=r"((r)[23]), \
          "=r"((r)[24]), "=r"((r)[25]), "=r"((r)[26]), "=r"((r)[27]), \
          "=r"((r)[28]), "=r"((r)[29]), "=r"((r)[30]), "=r"((r)[31]) \
        : "r"(ta))

static constexpr uint64_t SMEM_DESC_BASE_SW128 =
    (uint64_t(2)  << 61) | (uint64_t(1) << 46) | (uint64_t(64) << 32) | (uint64_t(1) << 16);
#define MAKE_SMEM_DESC(a) (SMEM_DESC_BASE_SW128 | ((uint64_t)((a) >> 4) & 0x3FFF))

// idesc kind::f16 cg2: dtype=F32, a/b=BF16, N=256, M=256
static constexpr uint32_t IDESC_BF16_CG2 =
    (1u << 4) | (1u << 7) | (1u << 10) | ((256u / 8) << 17) | ((256u / 16) << 24);

__device__ __forceinline__ void mma_bf16_ss_cg2(uint32_t d, uint64_t ad, uint64_t bd,
                                                uint32_t idesc, unsigned en) {
    asm volatile("{\n\t.reg .pred p;\n\tsetp.ne.u32 p, %5, 0;\n\t"
        "tcgen05.mma.cta_group::2.kind::f16 [%0], %1, %2, %3, "
        "{%4, %4, %4, %4, %4, %4, %4, %4}, p;\n\t}"
        :: "r"(d), "l"(ad), "l"(bd), "r"(idesc), "r"(0u), "r"(en) : "memory");
}
#endif // TC_OK

// ---------------------------------------------------------------------------
// Scratch
// ---------------------------------------------------------------------------
__device__ float    g_gate[B*D];
__device__ float    g_score[B*H];
__device__ __align__(16) unsigned char g_w1s[8*65536];   // bf16 w1^T SW128 images
__device__ int      g_flag_gt1 = 0;
__device__ int      g_flag_other = 0;

// ---------------------------------------------------------------------------
// Kernel S: merged setup — cvt_w1 / gate+zero-out / mask-dtype detect
// ---------------------------------------------------------------------------
__global__ void k_setup(const float* __restrict__ Kmat,
                        const float* __restrict__ W,
                        const float* __restrict__ w1,
                        const unsigned char* __restrict__ mask,
                        float* __restrict__ out) {
    const int blk = blockIdx.x;
    const int tid = threadIdx.x;
    if (blk < 128) {
        int lin = blk * 256 + tid;
        int n     = lin & 511;
        int kq    = (lin >> 9) & 7;
        int chunk = lin >> 12;
        int k0 = chunk*64 + kq*8;
        __nv_bfloat162 t[4];
        #pragma unroll
        for (int j = 0; j < 4; j++) {
            float f0 = w1[(k0 + 2*j    ) * HID + n];
            float f1 = w1[(k0 + 2*j + 1) * HID + n];
            t[j] = __floats2bfloat162_rn(f0, f1);
        }
        uint32_t off = (uint32_t)(n*128 + kq*16);
        *reinterpret_cast<uint4*>(g_w1s + chunk*65536 + SW128(off)) =
            *reinterpret_cast<uint4*>(t);
    } else if (blk < 256) {
        int i = (blk - 128) * 256 + tid;
        int k = i & 511;
        g_gate[i] = W[k*D + k] * Kmat[i];
        out[i] = 0.0f;
    } else {
        int lgt1 = 0, lother = 0;
        int base = (blk - 256) * 2048;
        for (int j = tid; j < 2048; j += 256) {
            int i = base + j;
            unsigned char v = mask[i];
            if (v > 1) lgt1 = 1;
            if (v != 0 && (i & 3) != 0) lother = 1;
        }
        if (__syncthreads_or(lgt1))   { if (tid == 0) atomicOr(&g_flag_gt1, 1); }
        if (__syncthreads_or(lother)) { if (tid == 0) atomicOr(&g_flag_other, 1); }
    }
}

// ---------------------------------------------------------------------------
// Kernel 1: persistent cg2 GEMM + fused relu/w2 epilogue -> g_score.
//   Exact R9 structure (proven); single change vs R9: epilogue drains TMEM
//   128 cols per WAIT_LD (4x LDTM) instead of 64/2 — halves serial TMEM
//   wait round-trips. No sync/pipeline changes.
// ---------------------------------------------------------------------------
// SMEM map:
#define OFF_TMEM    0
#define MB_MDONE(b) (8  + (b)*8)            // 8, 16
#define MB_BRDY(b)  (24 + (b)*8)            // 24, 32, 40
#define MB_TRDY(b)  (48 + (b)*8)            // 48, 56 (leader, count=2)
#define MB_EPID     64                       // leader, count=2
#define OFF_GATE    128                      // 512 f32
#define OFF_BIAS    2176                     // 512 f32
#define OFF_W2V     4224                     // 512 f32
#define OFF_A(b)    (8192  + (b)*16384)      // 2 x 16 KB bf16 A (SW128)
#define OFF_B(b)    (40960 + (b)*32768)      // 3 x 32 KB bf16 B-half (SW128)
#define SMEM_BYTES  139264

__global__ __launch_bounds__(256, 1) __cluster_dims__(2, 1, 1)
void k_gemm_tc(
        const float* __restrict__ V,
        const float* __restrict__ w1,
        const float* __restrict__ b1,
        const float* __restrict__ w2) {
    extern __shared__ char smem[];
    const int tid = threadIdx.x;

#if TC_OK
    // =================== persistent cg2 tcgen05 bf16 path ===================
    const uint32_t sb = smem_to_u32(smem);
    const int wid = tid >> 5;
    const int lid = tid & 31;
    const uint32_t rank = cluster_rank();
    const int cid = blockIdx.x >> 1;

    float* gs   = (float*)(smem + OFF_GATE);
    float* bias = (float*)(smem + OFF_BIAS);
    float* w2s  = (float*)(smem + OFF_W2V);
    for (int i = tid; i < D; i += 256) { bias[i] = b1[i]; w2s[i] = w2[i]; }

    if (wid == 0) TCGEN05_ALLOC_CG2(sb + OFF_TMEM, 512);
    if (tid == 0) {
        MBARRIER_INIT(sb + MB_MDONE(0), 1); MBARRIER_INIT(sb + MB_MDONE(1), 1);
        MBARRIER_INIT(sb + MB_BRDY(0), 1);  MBARRIER_INIT(sb + MB_BRDY(1), 1);
        MBARRIER_INIT(sb + MB_BRDY(2), 1);
        MBARRIER_INIT(sb + MB_TRDY(0), 2);  MBARRIER_INIT(sb + MB_TRDY(1), 2);
        MBARRIER_INIT(sb + MB_EPID, 2);
    }
    __syncthreads();
    CLUSTER_SYNC();

    uint32_t tmem;
    asm volatile("ld.shared.b32 %0, [%1];" : "=r"(tmem) : "r"(sb + OFF_TMEM));

    // B-half sources for this rank (rows [128r,128r+128) and [256+128r,384+128r))
    const unsigned char* bsrc0 = g_w1s + rank*16384;
    const unsigned char* bsrc1 = g_w1s + 32768 + rank*16384;

    const int kq  = tid & 7;
    const int mb_ = tid >> 3;

    int mdpar[2] = {0, 0};
    int bpar[3]  = {0, 0, 0};
    int tpar[2]  = {0, 0};
    int epar     = 0;
    int b3 = 0;              // global chunk counter mod 3
    bool first = true;
    float4 vreg[8];

    for (int t = cid; t < NTILES; t += NCLUSTERS) {
        const int row0 = t*256 + rank*128;
        const int b = row0 >> 11;
        const bool hasNext = (t + NCLUSTERS) < NTILES;
        const float* Vbase = V + (long long)row0 * D;

        // gate for this tile's batch
        for (int i = tid; i < D; i += 256) gs[i] = g_gate[b*D + i];
        __syncthreads();

        if (first) {
            // Prologue: B kchunks 0,1,2 into bufs 0,1,2; V chunk 0 into regs
            if (tid == 0) {
                #pragma unroll
                for (int c = 0; c < 3; c++) {
                    MBARRIER_EXPECT_TX(sb + MB_BRDY(c), 32768u);
                    CP_ASYNC_BULK(sb + OFF_B(c),         (const void*)(bsrc0 + c*65536),
                                  16384u, sb + MB_BRDY(c));
                    CP_ASYNC_BULK(sb + OFF_B(c) + 16384, (const void*)(bsrc1 + c*65536),
                                  16384u, sb + MB_BRDY(c));
                }
            }
            #pragma unroll
            for (int l = 0; l < 4; l++) {
                const float* p = Vbase + (long long)(mb_ + l*32)*D + kq*8;
                vreg[2*l]   = *reinterpret_cast<const float4*>(p);
                vreg[2*l+1] = *reinterpret_cast<const float4*>(p + 4);
            }
            first = false;
        } else {
            // B for kchunks 1,2 of this tile (bufs b3+1, b3+2 freed by epilogue)
            if (tid == 0) {
                #pragma unroll
                for (int c = 1; c <= 2; c++) {
                    int nb = b3 + c; nb -= (nb >= 3) ? 3 : 0;
                    MBARRIER_EXPECT_TX(sb + MB_BRDY(nb), 32768u);
                    CP_ASYNC_BULK(sb + OFF_B(nb),         (const void*)(bsrc0 + c*65536),
                                  16384u, sb + MB_BRDY(nb));
                    CP_ASYNC_BULK(sb + OFF_B(nb) + 16384, (const void*)(bsrc1 + c*65536),
                                  16384u, sb + MB_BRDY(nb));
                }
            }
            // vreg already holds this tile's chunk 0 (loaded at prev tile i==7)
        }

        for (int i = 0; i < 8; i++) {
            const int abuf = i & 1;
            if (i >= 2) {
                MBARRIER_WAIT_PARITY(sb + MB_MDONE(abuf), mdpar[abuf]);
                mdpar[abuf] ^= 1;
                // prefetch B for next global chunk (kchunk i+1, or 0 of next tile)
                if (tid == 0 && (i < 7 || hasNext)) {
                    int nk = (i + 1) & 7;
                    int nb = b3 + 1; nb -= (nb >= 3) ? 3 : 0;
                    MBARRIER_EXPECT_TX(sb + MB_BRDY(nb), 32768u);
                    CP_ASYNC_BULK(sb + OFF_B(nb),         (const void*)(bsrc0 + nk*65536),
                                  16384u, sb + MB_BRDY(nb));
                    CP_ASYNC_BULK(sb + OFF_B(nb) + 16384, (const void*)(bsrc1 + nk*65536),
                                  16384u, sb + MB_BRDY(nb));
                }
            }

            // Convert vreg (chunk i) -> A[abuf], gated, SW128
            {
                const float* gp = gs + i*64 + kq*8;
                float4 gA = *reinterpret_cast<const float4*>(gp);
                float4 gB = *reinterpret_cast<const float4*>(gp + 4);
                #pragma unroll
                for (int l = 0; l < 4; l++) {
                    int m = mb_ + l*32;
                    float4 v0 = vreg[2*l], v1 = vreg[2*l+1];
                    __nv_bfloat162 tt[4];
                    tt[0] = __floats2bfloat162_rn(v0.x*gA.x, v0.y*gA.y);
                    tt[1] = __floats2bfloat162_rn(v0.z*gA.z, v0.w*gA.w);
                    tt[2] = __floats2bfloat162_rn(v1.x*gB.x, v1.y*gB.y);
                    tt[3] = __floats2bfloat162_rn(v1.z*gB.z, v1.w*gB.w);
                    uint32_t off = (uint32_t)(m*128 + kq*16);
                    *reinterpret_cast<uint4*>(smem + OFF_A(abuf) + SW128(off)) =
                        *reinterpret_cast<uint4*>(tt);
                }
            }

            // Register prefetch of next chunk's V (same tile or next tile c0)
            if (i < 7) {
                #pragma unroll
                for (int l = 0; l < 4; l++) {
                    const float* p = Vbase + (long long)(mb_ + l*32)*D + (i+1)*64 + kq*8;
                    vreg[2*l]   = *reinterpret_cast<const float4*>(p);
                    vreg[2*l+1] = *reinterpret_cast<const float4*>(p + 4);
                }
            } else if (hasNext) {
                const float* nVbase = V + (long long)((t + NCLUSTERS)*256 + rank*128) * D;
                #pragma unroll
                for (int l = 0; l < 4; l++) {
                    const float* p = nVbase + (long long)(mb_ + l*32)*D + kq*8;
                    vreg[2*l]   = *reinterpret_cast<const float4*>(p);
                    vreg[2*l+1] = *reinterpret_cast<const float4*>(p + 4);
                }
            }

            FENCE_ASYNC_SHARED();
            __syncthreads();

            // Signal thread: local B ready + A stored -> arrive leader TRDY
            if (tid == 32) {
                MBARRIER_WAIT_PARITY(sb + MB_BRDY(b3), bpar[b3]);
                bpar[b3] ^= 1;
                MBARRIER_ARRIVE_CLUSTER(sb + MB_TRDY(abuf), 0);
            }

            // Leader: wait readiness (and prior tile's epilogue for i==0), MMA
            if (rank == 0 && wid == 0) {
                if (i == 0 && t != cid) {
                    MBARRIER_WAIT_PARITY_CLU(sb + MB_EPID, epar);
                    epar ^= 1;
                }
                MBARRIER_WAIT_PARITY_CLU(sb + MB_TRDY(abuf), tpar[abuf]);
                tpar[abuf] ^= 1;
                if (elect_one_pred()) {
                    uint64_t ad = MAKE_SMEM_DESC(sb + OFF_A(abuf));
                    uint64_t bd = MAKE_SMEM_DESC(sb + OFF_B(b3));
                    #pragma unroll
                    for (int ks = 0; ks < 4; ks++) {
                        unsigned en = (i > 0 || ks > 0) ? 1u : 0u;
                        mma_bf16_ss_cg2(tmem,       ad + ks*2, bd + ks*2,
                                        IDESC_BF16_CG2, en);
                        mma_bf16_ss_cg2(tmem + 256, ad + ks*2, bd + 1024 + ks*2,
                                        IDESC_BF16_CG2, en);
                    }
                    TCGEN05_COMMIT_MC_CG2(sb + MB_MDONE(abuf), 0x3);
                }
            }
            b3++; b3 -= (b3 >= 3) ? 3 : 0;
        }

        // Drain last two chunks' MMAs, then epilogue
        MBARRIER_WAIT_PARITY(sb + MB_MDONE(0), mdpar[0]); mdpar[0] ^= 1;
        MBARRIER_WAIT_PARITY(sb + MB_MDONE(1), mdpar[1]); mdpar[1] ^= 1;
        TCGEN05_FENCE_AFTER();

        if (wid < 4) {
            float s = 0.0f;
            #pragma unroll 1
            for (int c = 0; c < HID; c += 128) {
                uint32_t r0[32], r1[32], r2[32], r3[32];
                TCGEN05_LD_32X32B_X32(r0, tmem + c);
                TCGEN05_LD_32X32B_X32(r1, tmem + c + 32);
                TCGEN05_LD_32X32B_X32(r2, tmem + c + 64);
                TCGEN05_LD_32X32B_X32(r3, tmem + c + 96);
                TCGEN05_WAIT_LD();
                #pragma unroll
                for (int j = 0; j < 32; j++) {
                    float v0 = __uint_as_float(r0[j]) + bias[c + j];
                    float v1 = __uint_as_float(r1[j]) + bias[c + 32 + j];
                    float v2 = __uint_as_float(r2[j]) + bias[c + 64 + j];
                    float v3 = __uint_as_float(r3[j]) + bias[c + 96 + j];
                    s += fmaxf(v0, 0.0f) * w2s[c + j];
                    s += fmaxf(v1, 0.0f) * w2s[c + 32 + j];
                    s += fmaxf(v2, 0.0f) * w2s[c + 64 + j];
                    s += fmaxf(v3, 0.0f) * w2s[c + 96 + j];
                }
            }
            TCGEN05_FENCE_BEFORE();
            g_score[row0 + wid*32 + lid] = s;
        }
        __syncthreads();
        // Tell leader both CTAs' epilogues are done (D may be overwritten)
        if (hasNext && tid == 32)
            MBARRIER_ARRIVE_CLUSTER(sb + MB_EPID, 0);
    }

    CLUSTER_SYNC();
    if (wid == 0) {
        TCGEN05_RELINQUISH_CG2();
        TCGEN05_DEALLOC_CG2(tmem, 512);
    }
#else
    // ======================= f32x2 SGEMM fallback (persistent) =============
    float* Xs  = (float*)smem;
    float* Ws  = (float*)(smem + 128*20*4);
    float* gsh = (float*)(smem + 128*20*4 + 16*128*4);
    float* red = gsh + 512;
    const int tx = tid & 15;
    const int ty = tid >> 4;

    for (int mt = blockIdx.x; mt < M_TOTAL/128; mt += gridDim.x) {
        const int row0 = mt * 128;
        const int b = row0 >> 11;
        for (int i = tid; i < D; i += 256) gsh[i] = g_gate[b*D + i];
        __syncthreads();

        float scoreAcc[8];
        #pragma unroll
        for (int i = 0; i < 8; i++) scoreAcc[i] = 0.0f;

        const float* Vblk = V + (long long)row0 * D;

        for (int n0 = 0; n0 < HID; n0 += 128) {
            unsigned long long acc[8][4];
            #pragma unroll
            for (int i = 0; i < 8; i++)
                #pragma unroll
                for (int q = 0; q < 4; q++) acc[i][q] = 0ULL;

            for (int kk = 0; kk < D; kk += 16) {
                #pragma unroll
                for (int l = 0; l < 2; l++) {
                    int lin = tid + l*256;
                    int m   = lin >> 2;
                    int k4  = (lin & 3) << 2;
                    float4 v = *reinterpret_cast<const float4*>(
                                   &Vblk[(long long)m*D + kk + k4]);
                    Xs[m*20 + k4+0] = v.x; Xs[m*20 + k4+1] = v.y;
                    Xs[m*20 + k4+2] = v.z; Xs[m*20 + k4+3] = v.w;
                }
                #pragma unroll
                for (int l = 0; l < 2; l++) {
                    int lin = tid + l*256;
                    int k   = lin >> 5;
                    int n4  = (lin & 31) << 2;
                    float gk = gsh[kk + k];
                    float4 w = *reinterpret_cast<const float4*>(
                                   &w1[(long long)(kk+k)*HID + n0 + n4]);
                    Ws[k*128 + n4+0] = w.x*gk; Ws[k*128 + n4+1] = w.y*gk;
                    Ws[k*128 + n4+2] = w.z*gk; Ws[k*128 + n4+3] = w.w*gk;
                }
                __syncthreads();

                #pragma unroll
                for (int k = 0; k < 16; k++) {
                    unsigned long long bvec[4];
                    const unsigned long long* wr =
                        reinterpret_cast<const unsigned long long*>(&Ws[k*128 + tx*8]);
                    #pragma unroll
                    for (int q = 0; q < 4; q++) bvec[q] = wr[q];
                    #pragma unroll
                    for (int i = 0; i < 8; i++) {
                        float a = Xs[(ty*8 + i)*20 + k];
                        unsigned long long a2;
                        asm("mov.b64 %0, {%1, %1};" : "=l"(a2) : "f"(a));
                        #pragma unroll
                        for (int q = 0; q < 4; q++)
                            asm("fma.rn.f32x2 %0, %1, %2, %0;"
                                : "+l"(acc[i][q]) : "l"(a2), "l"(bvec[q]));
                    }
                }
                __syncthreads();
            }

            float b1v[8], w2v[8];
            #pragma unroll
            for (int j = 0; j < 8; j++) {
                b1v[j] = b1[n0 + tx*8 + j];
                w2v[j] = w2[n0 + tx*8 + j];
            }
            #pragma unroll
            for (int i = 0; i < 8; i++) {
                float s = 0.0f;
                #pragma unroll
                for (int q = 0; q < 4; q++) {
                    float2 v = *reinterpret_cast<float2*>(&acc[i][q]);
                    float c0 = v.x + b1v[q*2+0];
                    float c1 = v.y + b1v[q*2+1];
                    s += fmaxf(c0, 0.0f) * w2v[q*2+0] + fmaxf(c1, 0.0f) * w2v[q*2+1];
                }
                scoreAcc[i] += s;
            }
        }

        #pragma unroll
        for (int i = 0; i < 8; i++) red[(ty*8 + i)*17 + tx] = scoreAcc[i];
        __syncthreads();
        if (tid < 128) {
            float s = 0.0f;
            #pragma unroll
            for (int tq = 0; tq < 16; tq++) s += red[tid*17 + tq];
            g_score[row0 + tid] = s;
        }
        __syncthreads();
    }
#endif
}

// ---------------------------------------------------------------------------
// Kernel 2: masked softmax over h per batch, alpha stored in place
// ---------------------------------------------------------------------------
__global__ __launch_bounds__(256) void k_softmax(const void* __restrict__ mask_raw) {
    const int b   = blockIdx.x;
    const int tid = threadIdx.x;
    __shared__ float sh[256];

    const int mode = g_flag_gt1 ? 2 : (g_flag_other ? 0 : 1);
    const unsigned char* m8  = (const unsigned char*)mask_raw;
    const int*           m32 = (const int*)mask_raw;
    const float*         mf  = (const float*)mask_raw;

    float s[8];
    float mx = -3.0e38f;
    #pragma unroll
    for (int l = 0; l < 8; l++) {
        int idx = b*H + tid + l*256;
        bool masked;
        if (mode == 1)      masked = (m32[idx] != 0);
        else if (mode == 2) masked = (mf[idx] != 0.0f);
        else                masked = (m8[idx] != 0);
        float v = g_score[idx];
        if (masked) v = MASK_FILL_F;
        s[l] = v;
        mx = fmaxf(mx, v);
    }
    sh[tid] = mx; __syncthreads();
    for (int off = 128; off > 0; off >>= 1) {
        if (tid < off) sh[tid] = fmaxf(sh[tid], sh[tid + off]);
        __syncthreads();
    }
    mx = sh[0];
    __syncthreads();

    float e[8], sum = 0.0f;
    #pragma unroll
    for (int l = 0; l < 8; l++) { e[l] = expf(s[l] - mx); sum += e[l]; }
    sh[tid] = sum; __syncthreads();
    for (int off = 128; off > 0; off >>= 1) {
        if (tid < off) sh[tid] += sh[tid + off];
        __syncthreads();
    }
    float inv = 1.0f / sh[0];
    #pragma unroll
    for (int l = 0; l < 8; l++) g_score[b*H + tid + l*256] = e[l] * inv;
}

// ---------------------------------------------------------------------------
// Kernel 3: attn[b,d] = sum_h alpha[b,h] * V[b,h,d]   (R9-proven)
// ---------------------------------------------------------------------------
__global__ __launch_bounds__(128) void k_wsum(const float* __restrict__ V,
                                              float* __restrict__ out) {
    const int b   = blockIdx.x;
    const int h0  = blockIdx.y * 64;
    const int tid = threadIdx.x;
    __shared__ float al[64];
    if (tid < 64) al[tid] = g_score[b*H + h0 + tid];
    __syncthreads();

    const float4* Vb = reinterpret_cast<const float4*>(
        V + ((long long)b*H + h0) * D);
    float4 acc = make_float4(0.f, 0.f, 0.f, 0.f);
    #pragma unroll 8
    for (int h = 0; h < 64; h++) {
        float a = al[h];
        float4 v = Vb[(long long)h*128 + tid];
        acc.x = fmaf(a, v.x, acc.x);
        acc.y = fmaf(a, v.y, acc.y);
        acc.z = fmaf(a, v.z, acc.z);
        acc.w = fmaf(a, v.w, acc.w);
    }
    float* o = out + b*D + tid*4;
    atomicAdd(o + 0, acc.x);
    atomicAdd(o + 1, acc.y);
    atomicAdd(o + 2, acc.z);
    atomicAdd(o + 3, acc.w);
}

// ---------------------------------------------------------------------------
extern "C" void kernel_launch(void* const* d_in, const int* in_sizes, int n_in,
                              void* d_out, int out_size) {
    const float* Kmat = (const float*)d_in[0];
    const float* V    = (const float*)d_in[1];
    const void*  mask = d_in[2];
    const float* W    = (const float*)d_in[3];
    const float* w1   = (const float*)d_in[4];
    const float* b1   = (const float*)d_in[5];
    const float* w2   = (const float*)d_in[6];
    // b2 is a uniform score shift -> softmax-invariant, unused.
    float* out = (float*)d_out;

    cudaFuncSetAttribute(k_gemm_tc, cudaFuncAttributeMaxDynamicSharedMemorySize,
                         SMEM_BYTES);

    k_setup<<<320, 256>>>(Kmat, W, w1, (const unsigned char*)mask, out);
    k_gemm_tc<<<NCLUSTERS*2, 256, SMEM_BYTES>>>(V, w1, b1, w2);
    k_softmax<<<B, 256>>>(mask);
    k_wsum<<<dim3(B, 32), 128>>>(V, out);
}